// round 5
// baseline (speedup 1.0000x reference)
#include <cuda_runtime.h>
#include <cuda_fp16.h>
#include <cuda_fp8.h>
#include <cstdint>
#include <math.h>

// Problem constants
#define B_BATCH 8
#define T_SEQ   2048
#define DIN     1024
#define DOUT    1024
#define M_TOTAL (B_BATCH * T_SEQ)   // 16384
#define GAMMA_F 0.9865f

// Scan chunking
#define NCH 64
#define CHUNK (T_SEQ / NCH)         // 32

// lo-term scales (dodge e4m3 subnormal floor)
#define XQ_LO_SCALE 4096.0f         // 2^12
#define SV_LO_SCALE 16.0f           // 2^4
#define W8_SCALE    32.0f           // 2^5
#define Q_FOLD      (1.0f / 131072.0f)   // 2^-17
#define S_FOLD      (1.0f / 512.0f)      // 2^-9

// GEMM tiling: CTA 128x128, K-chunk 32, 8 warps (2x4), warp tile 64x32
#define SMEM_STRIDE 40                       // fp16 elems/row (32+8 pad) = 80 B
#define F8_STRIDE   48                       // bytes/row for fp8 tiles (32+16 pad)
#define AH_OFF      0
#define BH_OFF      10240
#define AL_OFF      20480
#define B8_OFF      26624
#define STAGE_BYTES 32768
#define NST 3
#define SMEM_TOTAL  (NST * STAGE_BYTES)      // 98304
#define NSTAGES 64                           // 2 GEMMs x 32 k-chunks

// ---------------- device scratch ----------------
__device__ float g_wksum[DIN];
__device__ float g_ksum[M_TOTAL];
__device__ float g_carry[B_BATCH][NCH][DIN];
__device__ __half g_xq_hi[(size_t)M_TOTAL * DIN];
__device__ unsigned char g_xq_lo8[(size_t)M_TOTAL * DIN];
__device__ __half g_sv_hi[(size_t)M_TOTAL * DIN];
__device__ unsigned char g_sv_lo8[(size_t)M_TOTAL * DIN];
__device__ __half g_wqt_hi[(size_t)DIN * DOUT];       // [n][k]
__device__ __half g_wvt_hi[(size_t)DIN * DOUT];
__device__ unsigned char g_wqt_8[(size_t)DIN * DOUT]; // [n][k], x32
__device__ unsigned char g_wvt_8[(size_t)DIN * DOUT];

// ---------------- helpers ----------------
__device__ __forceinline__ uint32_t smem_u32(const void* p) {
    uint32_t a;
    asm("{ .reg .u64 t; cvta.to.shared.u64 t, %1; cvt.u32.u64 %0, t; }" : "=r"(a) : "l"(p));
    return a;
}
__device__ __forceinline__ void cp16(uint32_t dst, const void* src) {
    asm volatile("cp.async.cg.shared.global [%0], [%1], 16;\n" :: "r"(dst), "l"(src));
}
__device__ __forceinline__ void ldsm_x4(uint32_t* r, uint32_t addr) {
    asm volatile("ldmatrix.sync.aligned.m8n8.x4.shared.b16 {%0,%1,%2,%3}, [%4];"
                 : "=r"(r[0]), "=r"(r[1]), "=r"(r[2]), "=r"(r[3]) : "r"(addr));
}
__device__ __forceinline__ void mma_f16(float* c, const uint32_t* a, const uint32_t* b) {
    asm volatile(
        "mma.sync.aligned.m16n8k16.row.col.f32.f16.f16.f32 "
        "{%0,%1,%2,%3},{%4,%5,%6,%7},{%8,%9},{%0,%1,%2,%3};\n"
        : "+f"(c[0]), "+f"(c[1]), "+f"(c[2]), "+f"(c[3])
        : "r"(a[0]), "r"(a[1]), "r"(a[2]), "r"(a[3]), "r"(b[0]), "r"(b[1]));
}
__device__ __forceinline__ void mma_f8(float* c, const uint32_t* a, const uint32_t* b) {
    asm volatile(
        "mma.sync.aligned.m16n8k32.row.col.f32.e4m3.e4m3.f32 "
        "{%0,%1,%2,%3},{%4,%5,%6,%7},{%8,%9},{%0,%1,%2,%3};\n"
        : "+f"(c[0]), "+f"(c[1]), "+f"(c[2]), "+f"(c[3])
        : "r"(a[0]), "r"(a[1]), "r"(a[2]), "r"(a[3]), "r"(b[0]), "r"(b[1]));
}
__device__ __forceinline__ unsigned char to_e4m3(float v) {
    return (unsigned char)__nv_cvt_float_to_fp8(v, __NV_SATFINITE, __NV_E4M3);
}

// ---------------- kernel 1: wksum[d] = sum_e Wk[d][e] ----------------
__global__ void wksum_kernel(const float* __restrict__ Wk) {
    int d = blockIdx.x;
    float s = 0.f;
    for (int e = threadIdx.x; e < DOUT; e += 256)
        s += Wk[(size_t)d * DOUT + e];
    __shared__ float red[256];
    red[threadIdx.x] = s;
    __syncthreads();
    for (int o = 128; o > 0; o >>= 1) {
        if (threadIdx.x < o) red[threadIdx.x] += red[threadIdx.x + o];
        __syncthreads();
    }
    if (threadIdx.x == 0) g_wksum[d] = red[0];
}

// ---------------- kernel 2 (fused prep): ksum; split xq; transpose+convert W ----------------
// blocks [0,2048):        ksum (8 warps x one row each)
// blocks [2048,18432):    split xq -> fp16 hi + scaled e4m3 lo
// blocks [18432,19456):   Wq transpose -> fp16 + e4m3(x32)
// blocks [19456,20480):   Wv transpose
__global__ void prep_kernel(const float* __restrict__ xk,
                            const float* __restrict__ xq,
                            const float* __restrict__ Wq,
                            const float* __restrict__ Wv) {
    int bx = blockIdx.x;
    int tid = threadIdx.x;
    __shared__ float tile[32][33];

    if (bx < 2048) {
        int warp = tid >> 5, lane = tid & 31;
        int m = bx * 8 + warp;
        const float4* row = (const float4*)(xk + (size_t)m * DIN);
        const float4* wk = (const float4*)g_wksum;
        float s = 0.f;
        #pragma unroll
        for (int it = 0; it < 8; it++) {
            float4 a = row[lane + it * 32], w = wk[lane + it * 32];
            s += a.x * w.x + a.y * w.y + a.z * w.z + a.w * w.w;
        }
        #pragma unroll
        for (int o = 16; o; o >>= 1)
            s += __shfl_xor_sync(0xFFFFFFFFu, s, o);
        if (lane == 0) {
            int t = m & (T_SEQ - 1);
            g_ksum[m] = (t == 0) ? 0.f : s;
        }
    } else if (bx < 18432) {
        size_t idx = (size_t)(bx - 2048) * 256 + tid;   // float4 index
        float4 v = ((const float4*)xq)[idx];
        float vv[4] = {v.x, v.y, v.z, v.w};
        __half h[4];
        unsigned char l8[4];
        #pragma unroll
        for (int j = 0; j < 4; j++) {
            h[j] = __float2half_rn(vv[j]);
            l8[j] = to_e4m3((vv[j] - __half2float(h[j])) * XQ_LO_SCALE);
        }
        ((uint2*)g_xq_hi)[idx] = *(uint2*)h;
        ((uint32_t*)g_xq_lo8)[idx] = *(uint32_t*)l8;
    } else {
        int b = bx - 18432;
        const float* W = (b < 1024) ? Wq : Wv;
        __half* Th = (b < 1024) ? g_wqt_hi : g_wvt_hi;
        unsigned char* T8 = (b < 1024) ? g_wqt_8 : g_wvt_8;
        b &= 1023;
        int n0 = (b & 31) * 32, k0 = (b >> 5) * 32;
        int tx = tid & 31, ty = tid >> 5;
        for (int i = ty; i < 32; i += 8)
            tile[i][tx] = W[(size_t)(k0 + i) * DOUT + n0 + tx];
        __syncthreads();
        for (int i = ty; i < 32; i += 8) {
            float v = tile[tx][i];
            size_t o = (size_t)(n0 + i) * DIN + k0 + tx;
            Th[o] = __float2half_rn(v);
            T8[o] = to_e4m3(v * W8_SCALE);
        }
    }
}

// ---------------- kernel 3: per-chunk carries (float2 per thread) ----------------
__global__ void scan_carry(const float* __restrict__ xv) {
    int ch = blockIdx.x, b = blockIdx.y;
    int d0 = blockIdx.z * 512 + threadIdx.x * 2;
    const float* base = xv + ((size_t)b * T_SEQ + (size_t)ch * CHUNK) * DIN + d0;
    const float* ks = g_ksum + b * T_SEQ + ch * CHUNK;
    float s0 = 0.f, s1 = 0.f;
    #pragma unroll 8
    for (int t = 0; t < CHUNK; t++) {
        float2 v = *(const float2*)(base + (size_t)t * DIN);
        float k = ks[t];
        s0 = GAMMA_F * s0 + k * v.x;
        s1 = GAMMA_F * s1 + k * v.y;
    }
    *(float2*)&g_carry[b][ch][d0] = make_float2(s0, s1);
}

// ---------------- kernel 4: combine carries + write sv (fp16 hi + e4m3 lo) ----------------
__global__ void scan_apply(const float* __restrict__ xv, float gammaC) {
    int ch = blockIdx.x, b = blockIdx.y;
    int d0 = blockIdx.z * 512 + threadIdx.x * 2;
    float s0 = 0.f, s1 = 0.f;
    for (int j = 0; j < ch; j++) {
        float2 c = *(const float2*)&g_carry[b][j][d0];
        s0 = s0 * gammaC + c.x;
        s1 = s1 * gammaC + c.y;
    }
    size_t base_off = ((size_t)b * T_SEQ + (size_t)ch * CHUNK) * DIN + d0;
    const float* base = xv + base_off;
    const float* ks = g_ksum + b * T_SEQ + ch * CHUNK;
    #pragma unroll 8
    for (int t = 0; t < CHUNK; t++) {
        float2 v = *(const float2*)(base + (size_t)t * DIN);
        float k = ks[t];
        s0 = GAMMA_F * s0 + k * v.x;
        s1 = GAMMA_F * s1 + k * v.y;
        __half h0 = __float2half_rn(s0), h1 = __float2half_rn(s1);
        unsigned char l0 = to_e4m3((s0 - __half2float(h0)) * SV_LO_SCALE);
        unsigned char l1 = to_e4m3((s1 - __half2float(h1)) * SV_LO_SCALE);
        size_t o = base_off + (size_t)t * DIN;
        __half hh[2] = {h0, h1};
        *(uint32_t*)(g_sv_hi + o) = *(uint32_t*)hh;
        unsigned char ll[2] = {l0, l1};
        *(unsigned short*)(g_sv_lo8 + o) = *(unsigned short*)ll;
    }
}

// ---------------- fused dual GEMM: O = (xq@Wq) .* (sv@Wv) ----------------
// main term fp16 HMMA (Ah*Bh) + correction e4m3 QMMA k32 ((Al*sc)*(B*sc')),
// folded into main acc once per GEMM phase. 3-stage cp.async pipeline.

__device__ __forceinline__ void load_tile_f16(uint32_t sbase, const __half* g,
                                              int row0, int k0, int tid) {
    const char* gb = (const char*)(g + (size_t)row0 * DIN + k0);
    #pragma unroll
    for (int i = 0; i < 2; i++) {
        int slot = tid + i * 256;
        int r = slot >> 2, c = slot & 3;
        cp16(sbase + (uint32_t)(r * (SMEM_STRIDE * 2) + c * 16),
             gb + (size_t)r * (DIN * 2) + c * 16);
    }
}
__device__ __forceinline__ void load_tile_f8(uint32_t sbase, const unsigned char* g,
                                             int row0, int k0, int tid) {
    const char* gb = (const char*)(g + (size_t)row0 * DIN + k0);
    int r = tid >> 1, c = tid & 1;
    cp16(sbase + (uint32_t)(r * F8_STRIDE + c * 16),
         gb + (size_t)r * DIN + c * 16);
}

__device__ __forceinline__ void mma_stage(uint32_t bufb, float acc[4][4][4],
                                          float accLo[4][4][4],
                                          int wm, int wn, int lane) {
    const int arow = lane & 15;
    const int acol8 = (lane >> 4) * 8;                      // fp16 A: k half (units)
    const int bnrow = ((lane >> 4) & 1) * 8 + (lane & 7);   // fp16 B: n within 16
    const int bcol8 = ((lane >> 3) & 1) * 8;                // fp16 B: k half

    uint32_t Ah = bufb + AH_OFF;
    uint32_t Bh = bufb + BH_OFF;
    uint32_t Al = bufb + AL_OFF;
    uint32_t B8 = bufb + B8_OFF;

    // ---- fp8 correction: one k32 pass ----
    {
        uint32_t a8[4][4], b8[4][2];
        #pragma unroll
        for (int i = 0; i < 4; i++) {
            uint32_t aoff = (uint32_t)((wm * 64 + i * 16 + arow) * F8_STRIDE
                                       + (lane >> 4) * 16);
            ldsm_x4(a8[i], Al + aoff);
        }
        #pragma unroll
        for (int j0 = 0; j0 < 4; j0 += 2) {
            uint32_t boff = (uint32_t)((wn * 32 + j0 * 8 + bnrow) * F8_STRIDE
                                       + ((lane >> 3) & 1) * 16);
            uint32_t br[4];
            ldsm_x4(br, B8 + boff);
            b8[j0][0] = br[0]; b8[j0][1] = br[1];
            b8[j0 + 1][0] = br[2]; b8[j0 + 1][1] = br[3];
        }
        #pragma unroll
        for (int i = 0; i < 4; i++)
            #pragma unroll
            for (int j = 0; j < 4; j++)
                mma_f8(accLo[i][j], a8[i], b8[j]);
    }

    // ---- fp16 main: two k16 passes ----
    #pragma unroll
    for (int kk = 0; kk < 32; kk += 16) {
        uint32_t ah[4][4], bh[4][2];
        #pragma unroll
        for (int i = 0; i < 4; i++) {
            uint32_t aoff = (uint32_t)((wm * 64 + i * 16 + arow) * (SMEM_STRIDE * 2)
                                       + (kk + acol8) * 2);
            ldsm_x4(ah[i], Ah + aoff);
        }
        #pragma unroll
        for (int j0 = 0; j0 < 4; j0 += 2) {
            uint32_t boff = (uint32_t)((wn * 32 + j0 * 8 + bnrow) * (SMEM_STRIDE * 2)
                                       + (kk + bcol8) * 2);
            uint32_t br[4];
            ldsm_x4(br, Bh + boff);
            bh[j0][0] = br[0]; bh[j0][1] = br[1];
            bh[j0 + 1][0] = br[2]; bh[j0 + 1][1] = br[3];
        }
        #pragma unroll
        for (int i = 0; i < 4; i++)
            #pragma unroll
            for (int j = 0; j < 4; j++)
                mma_f16(acc[i][j], ah[i], bh[j]);
    }
}

__global__ __launch_bounds__(256, 1) void qs_gemm(float* __restrict__ out) {
    extern __shared__ char smem[];
    uint32_t sb = smem_u32(smem);
    const int tid = threadIdx.x;
    const int warp = tid >> 5, lane = tid & 31;
    const int wm = warp >> 2, wn = warp & 3;
    const int g = lane >> 2, tg = lane & 3;
    const int row0 = blockIdx.y * 128;
    const int n0 = blockIdx.x * 128;

    float accQ[4][4][4], accS[4][4][4], accLo[4][4][4];
    #pragma unroll
    for (int i = 0; i < 4; i++)
        #pragma unroll
        for (int j = 0; j < 4; j++)
            #pragma unroll
            for (int k = 0; k < 4; k++) {
                accQ[i][j][k] = 0.f; accS[i][j][k] = 0.f; accLo[i][j][k] = 0.f;
            }

    auto issue = [&](int s) {
        if (s < NSTAGES) {
            int k0 = (s & 31) * 32;
            uint32_t bufb = sb + (uint32_t)(s % NST) * STAGE_BYTES;
            const __half *Ah, *Bh;
            const unsigned char *Al, *B8;
            if (s < 32) { Ah = g_xq_hi; Bh = g_wqt_hi; Al = g_xq_lo8; B8 = g_wqt_8; }
            else        { Ah = g_sv_hi; Bh = g_wvt_hi; Al = g_sv_lo8; B8 = g_wvt_8; }
            load_tile_f16(bufb + AH_OFF, Ah, row0, k0, tid);
            load_tile_f16(bufb + BH_OFF, Bh, n0,  k0, tid);
            load_tile_f8(bufb + AL_OFF, Al, row0, k0, tid);
            load_tile_f8(bufb + B8_OFF, B8, n0,  k0, tid);
        }
        asm volatile("cp.async.commit_group;\n" ::: "memory");
    };

    issue(0);
    issue(1);

    for (int s = 0; s < NSTAGES; s++) {
        asm volatile("cp.async.wait_group 1;\n" ::: "memory");
        __syncthreads();
        issue(s + 2);
        uint32_t bufb = sb + (uint32_t)(s % NST) * STAGE_BYTES;
        if (s < 32) mma_stage(bufb, accQ, accLo, wm, wn, lane);
        else        mma_stage(bufb, accS, accLo, wm, wn, lane);
        if (s == 31) {
            #pragma unroll
            for (int i = 0; i < 4; i++)
                #pragma unroll
                for (int j = 0; j < 4; j++)
                    #pragma unroll
                    for (int k = 0; k < 4; k++) {
                        accQ[i][j][k] += accLo[i][j][k] * Q_FOLD;
                        accLo[i][j][k] = 0.f;
                    }
        }
    }
    #pragma unroll
    for (int i = 0; i < 4; i++)
        #pragma unroll
        for (int j = 0; j < 4; j++)
            #pragma unroll
            for (int k = 0; k < 4; k++)
                accS[i][j][k] += accLo[i][j][k] * S_FOLD;

    // epilogue: O = Q .* S
    #pragma unroll
    for (int i = 0; i < 4; i++) {
        #pragma unroll
        for (int j = 0; j < 4; j++) {
            int r = row0 + wm * 64 + i * 16;
            int c = n0 + wn * 32 + j * 8 + 2 * tg;
            float2 o0, o1;
            o0.x = accQ[i][j][0] * accS[i][j][0];
            o0.y = accQ[i][j][1] * accS[i][j][1];
            o1.x = accQ[i][j][2] * accS[i][j][2];
            o1.y = accQ[i][j][3] * accS[i][j][3];
            *(float2*)(out + (size_t)(r + g    ) * DOUT + c) = o0;
            *(float2*)(out + (size_t)(r + g + 8) * DOUT + c) = o1;
        }
    }
}

// ---------------- launch ----------------
extern "C" void kernel_launch(void* const* d_in, const int* in_sizes, int n_in,
                              void* d_out, int out_size)
{
    const float* xq = (const float*)d_in[0];
    const float* xk = (const float*)d_in[1];
    const float* xv = (const float*)d_in[2];
    const float* Wq = (const float*)d_in[3];
    const float* Wk = (const float*)d_in[4];
    const float* Wv = (const float*)d_in[5];
    float* out = (float*)d_out;

    float gammaC = (float)pow((double)GAMMA_F, (double)CHUNK);

    cudaFuncSetAttribute(qs_gemm, cudaFuncAttributeMaxDynamicSharedMemorySize, SMEM_TOTAL);

    wksum_kernel<<<DIN, 256>>>(Wk);                                   // 1
    prep_kernel<<<20480, 256>>>(xk, xq, Wq, Wv);                      // 2
    scan_carry<<<dim3(NCH, B_BATCH, 2), 256>>>(xv);                   // 3
    scan_apply<<<dim3(NCH, B_BATCH, 2), 256>>>(xv, gammaC);           // 4
    qs_gemm<<<dim3(DOUT / 128, M_TOTAL / 128), 256, SMEM_TOTAL>>>(out); // 5
}

// round 6
// speedup vs baseline: 1.7281x; 1.7281x over previous
#include <cuda_runtime.h>
#include <cuda_fp16.h>
#include <cstdint>
#include <math.h>

// Problem constants
#define B_BATCH 8
#define T_SEQ   2048
#define DIN     1024
#define DOUT    1024
#define M_TOTAL (B_BATCH * T_SEQ)   // 16384
#define GAMMA_F 0.9865f

// Scan chunking
#define NCH 64
#define CHUNK (T_SEQ / NCH)         // 32

// GEMM tiling: CTA 128x128, K-chunk 32 per stage (both GEMMs), 8 warps (2x4)
#define SMEM_STRIDE 40                       // fp16 elems/row (32+8 pad) = 80 B
#define TILE_EB     (128 * SMEM_STRIDE * 2)  // 10240 bytes
#define AQ_OFF      0
#define BQ_OFF      10240
#define AS_OFF      20480
#define BS_OFF      30720
#define STAGE_BYTES 40960
#define NST 3
#define SMEM_TOTAL  (NST * STAGE_BYTES)      // 122880
#define NSTAGES 32                           // 32 k-chunks, both GEMMs per stage

// ---------------- device scratch ----------------
__device__ float g_wksum[DIN];
__device__ float g_ksum[M_TOTAL];
__device__ float g_carry[B_BATCH][NCH][DIN];
__device__ __half g_xq_hi[(size_t)M_TOTAL * DIN];
__device__ __half g_sv_hi[(size_t)M_TOTAL * DIN];
__device__ __half g_wqt_hi[(size_t)DIN * DOUT];   // [n][k]
__device__ __half g_wvt_hi[(size_t)DIN * DOUT];

// ---------------- helpers ----------------
__device__ __forceinline__ uint32_t smem_u32(const void* p) {
    uint32_t a;
    asm("{ .reg .u64 t; cvta.to.shared.u64 t, %1; cvt.u32.u64 %0, t; }" : "=r"(a) : "l"(p));
    return a;
}
__device__ __forceinline__ void cp16(uint32_t dst, const void* src) {
    asm volatile("cp.async.cg.shared.global [%0], [%1], 16;\n" :: "r"(dst), "l"(src));
}
__device__ __forceinline__ void ldsm_x4(uint32_t* r, uint32_t addr) {
    asm volatile("ldmatrix.sync.aligned.m8n8.x4.shared.b16 {%0,%1,%2,%3}, [%4];"
                 : "=r"(r[0]), "=r"(r[1]), "=r"(r[2]), "=r"(r[3]) : "r"(addr));
}
__device__ __forceinline__ void mma_f16(float* c, const uint32_t* a, const uint32_t* b) {
    asm volatile(
        "mma.sync.aligned.m16n8k16.row.col.f32.f16.f16.f32 "
        "{%0,%1,%2,%3},{%4,%5,%6,%7},{%8,%9},{%0,%1,%2,%3};\n"
        : "+f"(c[0]), "+f"(c[1]), "+f"(c[2]), "+f"(c[3])
        : "r"(a[0]), "r"(a[1]), "r"(a[2]), "r"(a[3]), "r"(b[0]), "r"(b[1]));
}

// ---------------- kernel 1: wksum[d] = sum_e Wk[d][e] ----------------
__global__ void wksum_kernel(const float* __restrict__ Wk) {
    int d = blockIdx.x;
    float s = 0.f;
    for (int e = threadIdx.x; e < DOUT; e += 256)
        s += Wk[(size_t)d * DOUT + e];
    __shared__ float red[256];
    red[threadIdx.x] = s;
    __syncthreads();
    for (int o = 128; o > 0; o >>= 1) {
        if (threadIdx.x < o) red[threadIdx.x] += red[threadIdx.x + o];
        __syncthreads();
    }
    if (threadIdx.x == 0) g_wksum[d] = red[0];
}

// ---------------- kernel 2 (fused prep): ksum; xq->fp16; W transpose->fp16 ----------------
// blocks [0,2048):       ksum (8 warps x one row each)
// blocks [2048,18432):   xq -> fp16
// blocks [18432,19456):  Wq transpose
// blocks [19456,20480):  Wv transpose
__global__ void prep_kernel(const float* __restrict__ xk,
                            const float* __restrict__ xq,
                            const float* __restrict__ Wq,
                            const float* __restrict__ Wv) {
    int bx = blockIdx.x;
    int tid = threadIdx.x;
    __shared__ float tile[32][33];

    if (bx < 2048) {
        int warp = tid >> 5, lane = tid & 31;
        int m = bx * 8 + warp;
        const float4* row = (const float4*)(xk + (size_t)m * DIN);
        const float4* wk = (const float4*)g_wksum;
        float s = 0.f;
        #pragma unroll
        for (int it = 0; it < 8; it++) {
            float4 a = row[lane + it * 32], w = wk[lane + it * 32];
            s += a.x * w.x + a.y * w.y + a.z * w.z + a.w * w.w;
        }
        #pragma unroll
        for (int o = 16; o; o >>= 1)
            s += __shfl_xor_sync(0xFFFFFFFFu, s, o);
        if (lane == 0) {
            int t = m & (T_SEQ - 1);
            g_ksum[m] = (t == 0) ? 0.f : s;
        }
    } else if (bx < 18432) {
        size_t idx = (size_t)(bx - 2048) * 256 + tid;   // float4 index
        float4 v = ((const float4*)xq)[idx];
        __half h[4] = {__float2half_rn(v.x), __float2half_rn(v.y),
                       __float2half_rn(v.z), __float2half_rn(v.w)};
        ((uint2*)g_xq_hi)[idx] = *(uint2*)h;
    } else {
        int b = bx - 18432;
        const float* W = (b < 1024) ? Wq : Wv;
        __half* Th = (b < 1024) ? g_wqt_hi : g_wvt_hi;
        b &= 1023;
        int n0 = (b & 31) * 32, k0 = (b >> 5) * 32;
        int tx = tid & 31, ty = tid >> 5;
        for (int i = ty; i < 32; i += 8)
            tile[i][tx] = W[(size_t)(k0 + i) * DOUT + n0 + tx];
        __syncthreads();
        for (int i = ty; i < 32; i += 8)
            Th[(size_t)(n0 + i) * DIN + k0 + tx] = __float2half_rn(tile[tx][i]);
    }
}

// ---------------- kernel 3: per-chunk carries (float4 per thread) ----------------
__global__ void scan_carry(const float* __restrict__ xv) {
    int ch = blockIdx.x, b = blockIdx.y;
    int d0 = threadIdx.x * 4;
    const float* base = xv + ((size_t)b * T_SEQ + (size_t)ch * CHUNK) * DIN + d0;
    const float* ks = g_ksum + b * T_SEQ + ch * CHUNK;
    float s0 = 0.f, s1 = 0.f, s2 = 0.f, s3 = 0.f;
    #pragma unroll 8
    for (int t = 0; t < CHUNK; t++) {
        float4 v = *(const float4*)(base + (size_t)t * DIN);
        float k = ks[t];
        s0 = GAMMA_F * s0 + k * v.x;
        s1 = GAMMA_F * s1 + k * v.y;
        s2 = GAMMA_F * s2 + k * v.z;
        s3 = GAMMA_F * s3 + k * v.w;
    }
    *(float4*)&g_carry[b][ch][d0] = make_float4(s0, s1, s2, s3);
}

// ---------------- kernel 4: combine carries + write sv (fp16) ----------------
__global__ void scan_apply(const float* __restrict__ xv, float gammaC) {
    int ch = blockIdx.x, b = blockIdx.y;
    int d0 = threadIdx.x * 4;
    float s0 = 0.f, s1 = 0.f, s2 = 0.f, s3 = 0.f;
    for (int j = 0; j < ch; j++) {
        float4 c = *(const float4*)&g_carry[b][j][d0];
        s0 = s0 * gammaC + c.x;
        s1 = s1 * gammaC + c.y;
        s2 = s2 * gammaC + c.z;
        s3 = s3 * gammaC + c.w;
    }
    size_t base_off = ((size_t)b * T_SEQ + (size_t)ch * CHUNK) * DIN + d0;
    const float* base = xv + base_off;
    const float* ks = g_ksum + b * T_SEQ + ch * CHUNK;
    #pragma unroll 8
    for (int t = 0; t < CHUNK; t++) {
        float4 v = *(const float4*)(base + (size_t)t * DIN);
        float k = ks[t];
        s0 = GAMMA_F * s0 + k * v.x;
        s1 = GAMMA_F * s1 + k * v.y;
        s2 = GAMMA_F * s2 + k * v.z;
        s3 = GAMMA_F * s3 + k * v.w;
        __half h[4] = {__float2half_rn(s0), __float2half_rn(s1),
                       __float2half_rn(s2), __float2half_rn(s3)};
        *(uint2*)(g_sv_hi + base_off + (size_t)t * DIN) = *(uint2*)h;
    }
}

// ---------------- fused dual GEMM: O = (xq@Wq) .* (sv@Wv), pure fp16 ----------------

__device__ __forceinline__ void load_tile_f16(uint32_t sbase, const __half* g,
                                              int row0, int k0, int tid) {
    const char* gb = (const char*)(g + (size_t)row0 * DIN + k0);
    #pragma unroll
    for (int i = 0; i < 2; i++) {
        int slot = tid + i * 256;
        int r = slot >> 2, c = slot & 3;
        cp16(sbase + (uint32_t)(r * (SMEM_STRIDE * 2) + c * 16),
             gb + (size_t)r * (DIN * 2) + c * 16);
    }
}

__device__ __forceinline__ void mma_pass(uint32_t Abase, uint32_t Bbase,
                                         float acc[4][4][4], int wm, int wn, int lane) {
    const int arow = lane & 15;
    const int acol8 = (lane >> 4) * 8;
    const int bnrow = ((lane >> 4) & 1) * 8 + (lane & 7);
    const int bcol8 = ((lane >> 3) & 1) * 8;

    #pragma unroll
    for (int kk = 0; kk < 32; kk += 16) {
        uint32_t ah[4][4], bh[4][2];
        #pragma unroll
        for (int i = 0; i < 4; i++) {
            uint32_t aoff = (uint32_t)((wm * 64 + i * 16 + arow) * (SMEM_STRIDE * 2)
                                       + (kk + acol8) * 2);
            ldsm_x4(ah[i], Abase + aoff);
        }
        #pragma unroll
        for (int j0 = 0; j0 < 4; j0 += 2) {
            uint32_t boff = (uint32_t)((wn * 32 + j0 * 8 + bnrow) * (SMEM_STRIDE * 2)
                                       + (kk + bcol8) * 2);
            uint32_t br[4];
            ldsm_x4(br, Bbase + boff);
            bh[j0][0] = br[0]; bh[j0][1] = br[1];
            bh[j0 + 1][0] = br[2]; bh[j0 + 1][1] = br[3];
        }
        #pragma unroll
        for (int i = 0; i < 4; i++)
            #pragma unroll
            for (int j = 0; j < 4; j++)
                mma_f16(acc[i][j], ah[i], bh[j]);
    }
}

__global__ __launch_bounds__(256, 1) void qs_gemm(float* __restrict__ out) {
    extern __shared__ char smem[];
    uint32_t sb = smem_u32(smem);
    const int tid = threadIdx.x;
    const int warp = tid >> 5, lane = tid & 31;
    const int wm = warp >> 2, wn = warp & 3;
    const int g = lane >> 2, tg = lane & 3;
    const int row0 = blockIdx.y * 128;
    const int n0 = blockIdx.x * 128;

    float accQ[4][4][4], accS[4][4][4];
    #pragma unroll
    for (int i = 0; i < 4; i++)
        #pragma unroll
        for (int j = 0; j < 4; j++)
            #pragma unroll
            for (int k = 0; k < 4; k++) { accQ[i][j][k] = 0.f; accS[i][j][k] = 0.f; }

    auto issue = [&](int s) {
        if (s < NSTAGES) {
            int k0 = s * 32;
            uint32_t bufb = sb + (uint32_t)(s % NST) * STAGE_BYTES;
            load_tile_f16(bufb + AQ_OFF, g_xq_hi,  row0, k0, tid);
            load_tile_f16(bufb + BQ_OFF, g_wqt_hi, n0,  k0, tid);
            load_tile_f16(bufb + AS_OFF, g_sv_hi,  row0, k0, tid);
            load_tile_f16(bufb + BS_OFF, g_wvt_hi, n0,  k0, tid);
        }
        asm volatile("cp.async.commit_group;\n" ::: "memory");
    };

    issue(0);
    issue(1);

    for (int s = 0; s < NSTAGES; s++) {
        asm volatile("cp.async.wait_group 1;\n" ::: "memory");
        __syncthreads();
        issue(s + 2);
        uint32_t bufb = sb + (uint32_t)(s % NST) * STAGE_BYTES;
        mma_pass(bufb + AQ_OFF, bufb + BQ_OFF, accQ, wm, wn, lane);
        mma_pass(bufb + AS_OFF, bufb + BS_OFF, accS, wm, wn, lane);
    }

    // epilogue: O = Q .* S
    #pragma unroll
    for (int i = 0; i < 4; i++) {
        #pragma unroll
        for (int j = 0; j < 4; j++) {
            int r = row0 + wm * 64 + i * 16;
            int c = n0 + wn * 32 + j * 8 + 2 * tg;
            float2 o0, o1;
            o0.x = accQ[i][j][0] * accS[i][j][0];
            o0.y = accQ[i][j][1] * accS[i][j][1];
            o1.x = accQ[i][j][2] * accS[i][j][2];
            o1.y = accQ[i][j][3] * accS[i][j][3];
            *(float2*)(out + (size_t)(r + g    ) * DOUT + c) = o0;
            *(float2*)(out + (size_t)(r + g + 8) * DOUT + c) = o1;
        }
    }
}

// ---------------- launch ----------------
extern "C" void kernel_launch(void* const* d_in, const int* in_sizes, int n_in,
                              void* d_out, int out_size)
{
    const float* xq = (const float*)d_in[0];
    const float* xk = (const float*)d_in[1];
    const float* xv = (const float*)d_in[2];
    const float* Wq = (const float*)d_in[3];
    const float* Wk = (const float*)d_in[4];
    const float* Wv = (const float*)d_in[5];
    float* out = (float*)d_out;

    float gammaC = (float)pow((double)GAMMA_F, (double)CHUNK);

    cudaFuncSetAttribute(qs_gemm, cudaFuncAttributeMaxDynamicSharedMemorySize, SMEM_TOTAL);

    wksum_kernel<<<DIN, 256>>>(Wk);                                   // 1
    prep_kernel<<<20480, 256>>>(xk, xq, Wq, Wv);                      // 2
    scan_carry<<<dim3(NCH, B_BATCH), 256>>>(xv);                      // 3
    scan_apply<<<dim3(NCH, B_BATCH), 256>>>(xv, gammaC);              // 4
    qs_gemm<<<dim3(DOUT / 128, M_TOTAL / 128), 256, SMEM_TOTAL>>>(out); // 5
}